// round 15
// baseline (speedup 1.0000x reference)
#include <cuda_runtime.h>
#include <cuda_fp16.h>
#include <math.h>
#include <stdint.h>

// ---------------- problem constants ----------------
#define BB 2
#define SS 1024
#define TT 2048
#define HH 1024
#define NHD 8
#define NOPE 128
#define QHD 192
#define VD 128
#define QP 1024           // packed q cols (rope dims dropped)
#define KVC 2048
#define QKV 3072          // combined q|k|v columns
#define EE 8
#define CAP 2048
#define INTER 1024
#define SHD 1024

// ---------------- device scratch ----------------
// fp16 (attention path)
__device__ __half g_wqkv16[QKV * HH];     // rows [0,1024)=packed Wq, [1024,3072)=Wkv
__device__ __half g_wo16[HH * HH];
__device__ __half g_hnorm16[TT * HH];
__device__ __half g_qkv16[TT * QKV];      // cols: [0,1024)=q, [1024,2048)=k, [2048,3072)=v
__device__ __half g_attn16[TT * HH];
// fp32 (MoE path). "r" buffers are tf32-RNA-rounded (A operands); W fed raw.
__device__ float g_x1[TT * HH];
__device__ float g_h2[TT * HH];
__device__ float g_h2r[TT * HH];
__device__ float g_actr[TT * SHD];
__device__ float g_midr[(size_t)EE * CAP * INTER];
__device__ float g_sgui[2 * SHD * HH];    // interleaved rows (g0,u0,...), RNA-rounded
__device__ int   g_cnt[EE];
__device__ int   g_tok[EE * CAP];
__device__ float g_coef[EE * CAP];

// ---------------- helpers ----------------
__device__ __forceinline__ uint32_t s2u(const void* p) {
    return (uint32_t)__cvta_generic_to_shared(p);
}
__device__ __forceinline__ unsigned f2tf(float f) {
    unsigned r; asm("cvt.rna.tf32.f32 %0, %1;" : "=r"(r) : "f"(f)); return r;
}
__device__ __forceinline__ float f2tf_f(float f) {
    return __uint_as_float(f2tf(f));
}
__device__ __forceinline__ void mma_tf32(float* c, const unsigned* a, const unsigned* b) {
    asm volatile("mma.sync.aligned.m16n8k8.row.col.f32.tf32.tf32.f32 "
                 "{%0,%1,%2,%3},{%4,%5,%6,%7},{%8,%9},{%0,%1,%2,%3};"
                 : "+f"(c[0]), "+f"(c[1]), "+f"(c[2]), "+f"(c[3])
                 : "r"(a[0]), "r"(a[1]), "r"(a[2]), "r"(a[3]), "r"(b[0]), "r"(b[1]));
}
__device__ __forceinline__ void mma16(float* c, const unsigned* a, const unsigned* b) {
    asm volatile("mma.sync.aligned.m16n8k16.row.col.f32.f16.f16.f32 "
                 "{%0,%1,%2,%3},{%4,%5,%6,%7},{%8,%9},{%0,%1,%2,%3};"
                 : "+f"(c[0]), "+f"(c[1]), "+f"(c[2]), "+f"(c[3])
                 : "r"(a[0]), "r"(a[1]), "r"(a[2]), "r"(a[3]), "r"(b[0]), "r"(b[1]));
}
__device__ __forceinline__ void ldsm4(unsigned* r, uint32_t a) {
    asm volatile("ldmatrix.sync.aligned.m8n8.x4.shared.b16 {%0,%1,%2,%3},[%4];"
                 : "=r"(r[0]), "=r"(r[1]), "=r"(r[2]), "=r"(r[3]) : "r"(a));
}
__device__ __forceinline__ void ldsm4t(unsigned* r, uint32_t a) {
    asm volatile("ldmatrix.sync.aligned.m8n8.x4.trans.shared.b16 {%0,%1,%2,%3},[%4];"
                 : "=r"(r[0]), "=r"(r[1]), "=r"(r[2]), "=r"(r[3]) : "r"(a));
}
__device__ __forceinline__ void cpa16(uint32_t d, const void* s) {
    asm volatile("cp.async.cg.shared.global [%0], [%1], 16;" :: "r"(d), "l"(s));
}
__device__ __forceinline__ void cpa_commit() { asm volatile("cp.async.commit_group;"); }
template <int N> __device__ __forceinline__ void cpa_wait() {
    asm volatile("cp.async.wait_group %0;" :: "n"(N));
}
__device__ __forceinline__ unsigned h2u(__half2 h) { return *(unsigned*)&h; }

// ---------------- fused prologue kernel (single launch) ----------------
// blocks: [0,256) Wq-pack->wqkv[0:1024) | [256,768) Wkv->wqkv[1024:3072)
//         [768,1024) Wo->fp16 | [1024,1536) sgu interleave->tf32
//         [1536,3584) rmsnorm(x, ln1) -> g_hnorm16
__device__ __forceinline__ void cv16h(const float* __restrict__ sp, __half* __restrict__ dp) {
    float4 a0 = *(const float4*)sp;
    float4 a1 = *(const float4*)(sp + 4);
    float4 a2 = *(const float4*)(sp + 8);
    float4 a3 = *(const float4*)(sp + 12);
    __half2 h[8] = {__floats2half2_rn(a0.x, a0.y), __floats2half2_rn(a0.z, a0.w),
                    __floats2half2_rn(a1.x, a1.y), __floats2half2_rn(a1.z, a1.w),
                    __floats2half2_rn(a2.x, a2.y), __floats2half2_rn(a2.z, a2.w),
                    __floats2half2_rn(a3.x, a3.y), __floats2half2_rn(a3.z, a3.w)};
    *(uint4*)dp       = *(uint4*)h;
    *(uint4*)(dp + 8) = *(uint4*)(h + 4);
}
__global__ void fused_pro_k(const float* __restrict__ Wq, const float* __restrict__ Wkv,
                            const float* __restrict__ Wo, const float* __restrict__ sgu,
                            const float* __restrict__ x, const float* __restrict__ ln1) {
    int b = blockIdx.x, t = threadIdx.x;
    if (b < 256) {
        int i = (b * 256 + t) * 16;
        int r = i >> 10, c = i & 1023;
        int sr = (r >> 7) * QHD + (r & 127);     // drop rope rows
        cv16h(Wq + (size_t)sr * HH + c, g_wqkv16 + i);
    } else if (b < 768) {
        int i = ((b - 256) * 256 + t) * 16;
        cv16h(Wkv + i, g_wqkv16 + (size_t)QP * HH + i);
    } else if (b < 1024) {
        int i = ((b - 768) * 256 + t) * 16;
        cv16h(Wo + i, g_wo16 + i);
    } else if (b < 1536) {
        int i = ((b - 1024) * 256 + t) * 16;
        int row = i >> 10, c = i & 1023;
        int srow = (row & 1) ? (SHD + (row >> 1)) : (row >> 1);
        const float* sp = sgu + (size_t)srow * HH + c;
        float4 a = *(const float4*)sp;
        float4 bq = *(const float4*)(sp + 4);
        float4 cc = *(const float4*)(sp + 8);
        float4 d = *(const float4*)(sp + 12);
        *(float4*)(g_sgui + i)      = make_float4(f2tf_f(a.x), f2tf_f(a.y), f2tf_f(a.z), f2tf_f(a.w));
        *(float4*)(g_sgui + i + 4)  = make_float4(f2tf_f(bq.x), f2tf_f(bq.y), f2tf_f(bq.z), f2tf_f(bq.w));
        *(float4*)(g_sgui + i + 8)  = make_float4(f2tf_f(cc.x), f2tf_f(cc.y), f2tf_f(cc.z), f2tf_f(cc.w));
        *(float4*)(g_sgui + i + 12) = make_float4(f2tf_f(d.x), f2tf_f(d.y), f2tf_f(d.z), f2tf_f(d.w));
    } else {
        // rmsnorm row (attention input)
        int row = b - 1536;
        const float* xr = x + (size_t)row * HH;
        float v[4];
        float s = 0.f;
#pragma unroll
        for (int l = 0; l < 4; l++) {
            v[l] = xr[t + l * 256];
            s += v[l] * v[l];
        }
        __shared__ float red[256];
        red[t] = s;
        __syncthreads();
        for (int off = 128; off > 0; off >>= 1) {
            if (t < off) red[t] += red[t + off];
            __syncthreads();
        }
        float scale = rsqrtf(red[0] * (1.0f / HH) + 1e-6f);
#pragma unroll
        for (int l = 0; l < 4; l++) {
            int i = t + l * 256;
            g_hnorm16[(size_t)row * HH + i] = __float2half_rn(v[l] * scale * ln1[i]);
        }
    }
}

// ---------------- RMSNorm #2 (MoE input; also zeroes g_cnt) ----------------
__global__ void rmsnorm2_k(const float* __restrict__ x, const float* __restrict__ w,
                           float* __restrict__ y32, float* __restrict__ y32r) {
    int row = blockIdx.x;
    if (row == 0 && threadIdx.x < EE) g_cnt[threadIdx.x] = 0;
    const float* xr = x + (size_t)row * HH;
    float v[4];
    float s = 0.f;
#pragma unroll
    for (int l = 0; l < 4; l++) {
        v[l] = xr[threadIdx.x + l * 256];
        s += v[l] * v[l];
    }
    __shared__ float red[256];
    red[threadIdx.x] = s;
    __syncthreads();
    for (int off = 128; off > 0; off >>= 1) {
        if (threadIdx.x < off) red[threadIdx.x] += red[threadIdx.x + off];
        __syncthreads();
    }
    float scale = rsqrtf(red[0] * (1.0f / HH) + 1e-6f);
#pragma unroll
    for (int l = 0; l < 4; l++) {
        int i = threadIdx.x + l * 256;
        float o = v[l] * scale * w[i];
        y32[(size_t)row * HH + i] = o;
        y32r[(size_t)row * HH + i] = f2tf_f(o);
    }
}

// ================= tf32 GEMM (MoE path), 3-stage, raw-W =================
// C[M,N] = A[M,1024] @ W[N,1024]^T.  A RNA-rounded fp32; W raw fp32 (HW truncates).
// MODE 1 +residual / 2 expert-up silu->g_midr / 3 expert-down atomic
// MODE 5 fused gate_up+GLU: W rows interleaved (g,u); out = silu(g)*u -> g_actr
#define SMS 20
#define GTILE (128 * SMS)

template <int MODE>
__global__ void __launch_bounds__(256, 2) mma_gemm_k(
    const float* __restrict__ A, const float* __restrict__ W,
    float* __restrict__ C, int N, const float* __restrict__ R, size_t estride)
{
    extern __shared__ __align__(16) float dyn[];
    float* sA = dyn;                // [3][GTILE]
    float* sW = dyn + 3 * GTILE;    // [3][GTILE]
    __shared__ int   s_tok[128];
    __shared__ float s_cf[128];

    const int e  = blockIdx.z;
    const int m0 = blockIdx.y * 128;
    const int n0 = blockIdx.x * 128;
    const int tid = threadIdx.x;

    if (MODE == 2 || MODE == 3) {
        int n_e = g_cnt[e];
        if (m0 >= n_e) return;
        if (tid < 128) {
            int i = m0 + tid;
            bool ok = i < n_e;
            s_tok[tid] = ok ? g_tok[e * CAP + i] : -1;
            if (MODE == 3) s_cf[tid] = ok ? g_coef[e * CAP + i] : 0.f;
        }
        __syncthreads();
    }

    const float* Wbase = W + (size_t)e * estride + (size_t)n0 * 1024;
    const float* Arow  = (MODE == 3) ? (g_midr + ((size_t)e * CAP + m0) * 1024)
                                     : (A + (size_t)m0 * 1024);

    auto issue = [&](int stage, int it) {
        int k0 = it * 16;
        uint32_t da = s2u(sA + stage * GTILE);
        uint32_t dw = s2u(sW + stage * GTILE);
#pragma unroll
        for (int j = 0; j < 2; j++) {
            int q = tid + j * 256;
            int r = q >> 2, c4 = q & 3;
            const float* srcA;
            if (MODE == 2) {
                int tk = s_tok[r]; if (tk < 0) tk = 0;
                srcA = A + (size_t)tk * 1024 + k0 + c4 * 4;
            } else {
                srcA = Arow + (size_t)r * 1024 + k0 + c4 * 4;
            }
            uint32_t off = (uint32_t)(r * SMS + c4 * 4) * 4;
            cpa16(da + off, srcA);
            cpa16(dw + off, Wbase + (size_t)r * 1024 + k0 + c4 * 4);
        }
        cpa_commit();
    };

    const int wid = tid >> 5, lane = tid & 31;
    const int wm = wid & 3, wn = wid >> 2;
    const int lr = lane >> 2, lc = lane & 3;

    float acc[2][8][4] = {};

    issue(0, 0);
    issue(1, 1);
    for (int it = 0; it < 64; ++it) {
        int cur = it % 3;
        cpa_wait<1>();
        __syncthreads();
        if (it + 2 < 64) issue((it + 2) % 3, it + 2);
        const float* As = sA + cur * GTILE;
        const float* Ws = sW + cur * GTILE;
#pragma unroll
        for (int ks = 0; ks < 16; ks += 8) {
            unsigned af[2][4];
#pragma unroll
            for (int mt = 0; mt < 2; mt++) {
                int row = wm * 32 + mt * 16 + lr;
                int k = ks + lc;
                af[mt][0] = __float_as_uint(As[row * SMS + k]);
                af[mt][1] = __float_as_uint(As[(row + 8) * SMS + k]);
                af[mt][2] = __float_as_uint(As[row * SMS + k + 4]);
                af[mt][3] = __float_as_uint(As[(row + 8) * SMS + k + 4]);
            }
#pragma unroll
            for (int nt = 0; nt < 8; nt++) {
                int n = wn * 64 + nt * 8 + lr;
                int k = ks + lc;
                unsigned bf[2];
                bf[0] = __float_as_uint(Ws[n * SMS + k]);
                bf[1] = __float_as_uint(Ws[n * SMS + k + 4]);
                mma_tf32(acc[0][nt], af[0], bf);
                mma_tf32(acc[1][nt], af[1], bf);
            }
        }
    }

#pragma unroll
    for (int mt = 0; mt < 2; mt++)
#pragma unroll
    for (int i = 0; i < 2; i++) {
        int rloc = wm * 32 + mt * 16 + lr + i * 8;
#pragma unroll
        for (int nt = 0; nt < 8; nt++) {
            float v0 = acc[mt][nt][2 * i], v1 = acc[mt][nt][2 * i + 1];
            int col = n0 + wn * 64 + nt * 8 + 2 * lc;
            if (MODE == 1) {
                float2 rr = *(const float2*)&R[(size_t)(m0 + rloc) * N + col];
                *(float2*)&C[(size_t)(m0 + rloc) * N + col] = make_float2(v0 + rr.x, v1 + rr.y);
            } else if (MODE == 5) {
                float o = v0 / (1.f + __expf(-v0)) * v1;
                g_actr[(size_t)(m0 + rloc) * SHD + (col >> 1)] = f2tf_f(o);
            } else if (MODE == 2) {
                if (s_tok[rloc] >= 0) {
                    float o0 = v0 / (1.f + __expf(-v0));
                    float o1 = v1 / (1.f + __expf(-v1));
                    float* mr = g_midr + ((size_t)e * CAP + m0 + rloc) * 1024;
                    *(float2*)&mr[col] = make_float2(f2tf_f(o0), f2tf_f(o1));
                }
            } else {
                int tk = s_tok[rloc];
                if (tk >= 0) {
                    float cf = s_cf[rloc];
                    atomicAdd(&C[(size_t)tk * 1024 + col],     cf * v0);
                    atomicAdd(&C[(size_t)tk * 1024 + col + 1], cf * v1);
                }
            }
        }
    }
}

// ================= fp16 GEMM (attention path), 3-stage =================
// MODE 1: +residual fp32 out / MODE 4: fp16 out
#define HLDA 40
#define HTILE (128 * HLDA)

template <int MODE>
__global__ void __launch_bounds__(256, 2) hgemm_k(
    const __half* __restrict__ A, const __half* __restrict__ W,
    float* __restrict__ C, __half* __restrict__ C16,
    int N, const float* __restrict__ R)
{
    extern __shared__ __align__(16) __half hdyn[];
    __half* sA = hdyn;                 // [3][HTILE]
    __half* sW = hdyn + 3 * HTILE;

    const int m0 = blockIdx.y * 128;
    const int n0 = blockIdx.x * 128;
    const int tid = threadIdx.x;

    const __half* Wbase = W + (size_t)n0 * 1024;
    const __half* Arow  = A + (size_t)m0 * 1024;

    auto issue = [&](int stage, int it) {
        int k0 = it * 32;
        uint32_t da = s2u(sA + stage * HTILE);
        uint32_t dw = s2u(sW + stage * HTILE);
#pragma unroll
        for (int j = 0; j < 2; j++) {
            int q = tid + j * 256;
            int r = q >> 2, c4 = q & 3;
            uint32_t off = (uint32_t)(r * HLDA + c4 * 8) * 2;
            cpa16(da + off, Arow + (size_t)r * 1024 + k0 + c4 * 8);
            cpa16(dw + off, Wbase + (size_t)r * 1024 + k0 + c4 * 8);
        }
        cpa_commit();
    };

    const int wid = tid >> 5, lane = tid & 31;
    const int wm = wid & 3, wn = wid >> 2;
    const int lr = lane >> 2, lc = lane & 3;
    const int arow = lane & 15, ahalf = lane >> 4;
    const int bg = lane >> 3;
    const int brow = ((bg >> 1) << 3) + (lane & 7);
    const int bcol = (bg & 1) << 3;

    float acc[2][8][4] = {};

    issue(0, 0);
    issue(1, 1);
    for (int it = 0; it < 32; ++it) {
        int cur = it % 3;
        cpa_wait<1>();
        __syncthreads();
        if (it + 2 < 32) issue((it + 2) % 3, it + 2);
        const __half* As = sA + cur * HTILE;
        const __half* Ws = sW + cur * HTILE;
        uint32_t aBase = s2u(As) + (uint32_t)((wm * 32 + arow) * HLDA + ahalf * 8) * 2;
        uint32_t bBase = s2u(Ws) + (uint32_t)((wn * 64 + brow) * HLDA + bcol) * 2;
#pragma unroll
        for (int kc = 0; kc < 2; kc++) {
            unsigned av[2][4];
            ldsm4(av[0], aBase + kc * 32);
            ldsm4(av[1], aBase + kc * 32 + 16 * HLDA * 2);
#pragma unroll
            for (int np = 0; np < 4; np++) {
                unsigned bv[4];
                ldsm4(bv, bBase + kc * 32 + np * 16 * HLDA * 2);
                mma16(acc[0][2 * np],     av[0], bv);
                mma16(acc[0][2 * np + 1], av[0], bv + 2);
                mma16(acc[1][2 * np],     av[1], bv);
                mma16(acc[1][2 * np + 1], av[1], bv + 2);
            }
        }
    }

#pragma unroll
    for (int mt = 0; mt < 2; mt++)
#pragma unroll
    for (int i = 0; i < 2; i++) {
        int rloc = wm * 32 + mt * 16 + lr + i * 8;
#pragma unroll
        for (int nt = 0; nt < 8; nt++) {
            float v0 = acc[mt][nt][2 * i], v1 = acc[mt][nt][2 * i + 1];
            int col = n0 + wn * 64 + nt * 8 + 2 * lc;
            if (MODE == 1) {
                float2 rr = *(const float2*)&R[(size_t)(m0 + rloc) * N + col];
                *(float2*)&C[(size_t)(m0 + rloc) * N + col] = make_float2(v0 + rr.x, v1 + rr.y);
            } else {
                *(__half2*)&C16[(size_t)(m0 + rloc) * N + col] = __floats2half2_rn(v0, v1);
            }
        }
    }
}

// ================= fp16 flash attention (reads combined qkv buffer) =================
#define FLD 136
#define FL_SMEM ((64 + 128 + 128) * FLD * 2)   // 87040 B

__global__ void __launch_bounds__(128) flash16_k(const __half* __restrict__ qkv16,
                                                 __half* __restrict__ out16) {
    extern __shared__ __align__(16) __half fsm[];
    __half* Qs = fsm;
    __half* Ks = Qs + 64 * FLD;
    __half* Vs = Ks + 2 * 64 * FLD;

    const int b = blockIdx.z, h = blockIdx.y, qt = blockIdx.x;
    const int tid = threadIdx.x, wid = tid >> 5, lane = tid & 31;
    const int lr = lane >> 2, lc = lane & 3;
    const int t0 = b * SS + qt * 64;
    const float scale = rsqrtf((float)QHD);

    {
        uint32_t qb = s2u(Qs);
#pragma unroll
        for (int j = 0; j < 8; j++) {
            int q = tid + j * 128;
            int r = q >> 4, c = q & 15;
            cpa16(qb + (uint32_t)(r * FLD + c * 8) * 2,
                  qkv16 + (size_t)(t0 + r) * QKV + h * NOPE + c * 8);
        }
    }
    auto issue_kv = [&](int stage, int kt) {
        int k0g = b * SS + kt * 64;
        uint32_t kb = s2u(Ks + stage * 64 * FLD);
        uint32_t vb = s2u(Vs + stage * 64 * FLD);
#pragma unroll
        for (int j = 0; j < 8; j++) {
            int q = tid + j * 128;
            int r = q >> 4, c = q & 15;
            const __half* row = qkv16 + (size_t)(k0g + r) * QKV;
            cpa16(kb + (uint32_t)(r * FLD + c * 8) * 2, row + QP + h * NOPE + c * 8);
            cpa16(vb + (uint32_t)(r * FLD + c * 8) * 2, row + QP + NHD * NOPE + h * VD + c * 8);
        }
        cpa_commit();
    };
    issue_kv(0, 0);

    const int arow = lane & 15, ahalf = lane >> 4;
    const int bg = lane >> 3;
    const int brow = ((bg >> 1) << 3) + (lane & 7);
    const int bcol = (bg & 1) << 3;
    const int vrow = ((bg & 1) << 3) + (lane & 7);
    const int vcol = (bg >> 1) << 3;

    unsigned qf[8][4];
    float m0r = -1e30f, m1r = -1e30f, l0 = 0.f, l1 = 0.f;
    float o[16][4];
#pragma unroll
    for (int nt = 0; nt < 16; nt++)
#pragma unroll
        for (int j = 0; j < 4; j++) o[nt][j] = 0.f;

    for (int kt = 0; kt <= qt; kt++) {
        int cur = kt & 1;
        cpa_wait<0>();
        __syncthreads();
        if (kt < qt) issue_kv(cur ^ 1, kt + 1);
        if (kt == 0) {
            uint32_t qBase = s2u(Qs) + (uint32_t)((wid * 16 + arow) * FLD + ahalf * 8) * 2;
#pragma unroll
            for (int c = 0; c < 8; c++) ldsm4(qf[c], qBase + c * 32);
        }
        const __half* Kb = Ks + cur * 64 * FLD;
        const __half* Vb = Vs + cur * 64 * FLD;

        float sc[8][4] = {};
        uint32_t kBase = s2u(Kb) + (uint32_t)(brow * FLD + bcol) * 2;
#pragma unroll
        for (int c = 0; c < 8; c++) {
#pragma unroll
            for (int np = 0; np < 4; np++) {
                unsigned bv[4];
                ldsm4(bv, kBase + c * 32 + np * 16 * FLD * 2);
                mma16(sc[2 * np],     qf[c], bv);
                mma16(sc[2 * np + 1], qf[c], bv + 2);
            }
        }
#pragma unroll
        for (int nt = 0; nt < 8; nt++)
#pragma unroll
            for (int j = 0; j < 4; j++) sc[nt][j] *= scale;
        if (kt == qt) {
#pragma unroll
            for (int nt = 0; nt < 8; nt++)
#pragma unroll
                for (int j = 0; j < 4; j++) {
                    int colg = nt * 8 + 2 * lc + (j & 1);
                    int rowg = wid * 16 + lr + (j >> 1) * 8;
                    if (colg > rowg) sc[nt][j] = -1e30f;
                }
        }
        float mx0 = -1e30f, mx1 = -1e30f;
#pragma unroll
        for (int nt = 0; nt < 8; nt++) {
            mx0 = fmaxf(mx0, fmaxf(sc[nt][0], sc[nt][1]));
            mx1 = fmaxf(mx1, fmaxf(sc[nt][2], sc[nt][3]));
        }
        mx0 = fmaxf(mx0, __shfl_xor_sync(0xffffffffu, mx0, 1));
        mx0 = fmaxf(mx0, __shfl_xor_sync(0xffffffffu, mx0, 2));
        mx1 = fmaxf(mx1, __shfl_xor_sync(0xffffffffu, mx1, 1));
        mx1 = fmaxf(mx1, __shfl_xor_sync(0xffffffffu, mx1, 2));
        float mn0 = fmaxf(m0r, mx0), mn1 = fmaxf(m1r, mx1);
        float a0 = __expf(m0r - mn0), a1 = __expf(m1r - mn1);
        float s0 = 0.f, s1 = 0.f;
#pragma unroll
        for (int nt = 0; nt < 8; nt++) {
            sc[nt][0] = __expf(sc[nt][0] - mn0);
            sc[nt][1] = __expf(sc[nt][1] - mn0);
            sc[nt][2] = __expf(sc[nt][2] - mn1);
            sc[nt][3] = __expf(sc[nt][3] - mn1);
            s0 += sc[nt][0] + sc[nt][1];
            s1 += sc[nt][2] + sc[nt][3];
        }
        s0 += __shfl_xor_sync(0xffffffffu, s0, 1);
        s0 += __shfl_xor_sync(0xffffffffu, s0, 2);
        s1 += __shfl_xor_sync(0xffffffffu, s1, 1);
        s1 += __shfl_xor_sync(0xffffffffu, s1, 2);
        l0 = l0 * a0 + s0; l1 = l1 * a1 + s1;
        m0r = mn0; m1r = mn1;
#pragma unroll
        for (int nt = 0; nt < 16; nt++) {
            o[nt][0] *= a0; o[nt][1] *= a0;
            o[nt][2] *= a1; o[nt][3] *= a1;
        }
        uint32_t vBase = s2u(Vb) + (uint32_t)(vrow * FLD + vcol) * 2;
#pragma unroll
        for (int c = 0; c < 4; c++) {
            unsigned pa[4];
            pa[0] = h2u(__floats2half2_rn(sc[2 * c][0],     sc[2 * c][1]));
            pa[1] = h2u(__floats2half2_rn(sc[2 * c][2],     sc[2 * c][3]));
            pa[2] = h2u(__floats2half2_rn(sc[2 * c + 1][0], sc[2 * c + 1][1]));
            pa[3] = h2u(__floats2half2_rn(sc[2 * c + 1][2], sc[2 * c + 1][3]));
#pragma unroll
            for (int nv = 0; nv < 8; nv++) {
                unsigned bv[4];
                ldsm4t(bv, vBase + (uint32_t)(c * 16 * FLD + nv * 16) * 2);
                mma16(o[2 * nv],     pa, bv);
                mma16(o[2 * nv + 1], pa, bv + 2);
            }
        }
    }

    float inv0 = 1.f / l0, inv1 = 1.f / l1;
    int r0 = t0 + wid * 16 + lr, r1 = r0 + 8;
#pragma unroll
    for (int nt = 0; nt < 16; nt++) {
        int col = h * VD + nt * 8 + 2 * lc;
        *(__half2*)&out16[(size_t)r0 * HH + col] = __floats2half2_rn(o[nt][0] * inv0, o[nt][1] * inv0);
        *(__half2*)&out16[(size_t)r1 * HH + col] = __floats2half2_rn(o[nt][2] * inv1, o[nt][3] * inv1);
    }
}

// ---------------- router ----------------
__global__ void gate_k(const float* __restrict__ h2, const float* __restrict__ gw) {
    int warp = (blockIdx.x * blockDim.x + threadIdx.x) >> 5;
    int lane = threadIdx.x & 31;
    if (warp >= TT) return;
    const float* hr = h2 + (size_t)warp * HH;
    float hv[32];
#pragma unroll
    for (int i = 0; i < 32; i++) hv[i] = hr[lane + i * 32];
    float logits[EE];
#pragma unroll
    for (int e = 0; e < EE; e++) {
        const float* wr = gw + e * HH;
        float s = 0.f;
#pragma unroll
        for (int i = 0; i < 32; i++) s = fmaf(hv[i], wr[lane + i * 32], s);
#pragma unroll
        for (int off = 16; off >= 1; off >>= 1)
            s += __shfl_xor_sync(0xffffffffu, s, off);
        logits[e] = s;
    }
    if (lane == 0) {
        int i0 = 0; float v0 = logits[0];
#pragma unroll
        for (int e = 1; e < EE; e++)
            if (logits[e] > v0) { v0 = logits[e]; i0 = e; }
        int i1 = -1; float v1 = -1e30f;
#pragma unroll
        for (int e = 0; e < EE; e++)
            if (e != i0 && logits[e] > v1) { v1 = logits[e]; i1 = e; }
        float r = __expf(v1 - v0);
        float z = 1.f + r;
        float w0 = 1.f / z, w1 = r / z;
        int p0 = atomicAdd(&g_cnt[i0], 1);
        g_tok[i0 * CAP + p0] = warp; g_coef[i0 * CAP + p0] = w0;
        int p1 = atomicAdd(&g_cnt[i1], 1);
        g_tok[i1 * CAP + p1] = warp; g_coef[i1 * CAP + p1] = w1;
    }
}

// ---------------- launch ----------------
extern "C" void kernel_launch(void* const* d_in, const int* in_sizes, int n_in,
                              void* d_out, int out_size) {
    const float* x   = (const float*)d_in[0];
    const float* ln1 = (const float*)d_in[2];
    const float* ln2 = (const float*)d_in[3];
    const float* Wq  = (const float*)d_in[4];
    const float* Wkv = (const float*)d_in[5];
    const float* Wo  = (const float*)d_in[6];
    const float* gw  = (const float*)d_in[7];
    const float* w1  = (const float*)d_in[8];
    const float* w2  = (const float*)d_in[9];
    const float* sgu = (const float*)d_in[10];
    const float* sdn = (const float*)d_in[11];
    float* out = (float*)d_out;

    void *p_wqkv16, *p_wo16, *p_hn16, *p_qkv16, *p_attn16;
    void *p_x1, *p_h2, *p_h2r, *p_actr, *p_sgui;
    cudaGetSymbolAddress(&p_wqkv16, g_wqkv16);
    cudaGetSymbolAddress(&p_wo16,   g_wo16);
    cudaGetSymbolAddress(&p_hn16,   g_hnorm16);
    cudaGetSymbolAddress(&p_qkv16,  g_qkv16);
    cudaGetSymbolAddress(&p_attn16, g_attn16);
    cudaGetSymbolAddress(&p_x1,   g_x1);
    cudaGetSymbolAddress(&p_h2,   g_h2);
    cudaGetSymbolAddress(&p_h2r,  g_h2r);
    cudaGetSymbolAddress(&p_actr, g_actr);
    cudaGetSymbolAddress(&p_sgui, g_sgui);

    const int TF_SMEM = 6 * GTILE * 4;       // 61440 B
    const int H_SMEM  = 6 * HTILE * 2;       // 61440 B
    static bool s_attr = false;
    if (!s_attr) {
        s_attr = true;
        cudaFuncSetAttribute(mma_gemm_k<1>, cudaFuncAttributeMaxDynamicSharedMemorySize, TF_SMEM);
        cudaFuncSetAttribute(mma_gemm_k<2>, cudaFuncAttributeMaxDynamicSharedMemorySize, TF_SMEM);
        cudaFuncSetAttribute(mma_gemm_k<3>, cudaFuncAttributeMaxDynamicSharedMemorySize, TF_SMEM);
        cudaFuncSetAttribute(mma_gemm_k<5>, cudaFuncAttributeMaxDynamicSharedMemorySize, TF_SMEM);
        cudaFuncSetAttribute(hgemm_k<1>,    cudaFuncAttributeMaxDynamicSharedMemorySize, H_SMEM);
        cudaFuncSetAttribute(hgemm_k<4>,    cudaFuncAttributeMaxDynamicSharedMemorySize, H_SMEM);
        cudaFuncSetAttribute(flash16_k,     cudaFuncAttributeMaxDynamicSharedMemorySize, FL_SMEM);
    }

    // fused prologue: all weight conversions + first rmsnorm in one launch
    fused_pro_k<<<3584, 256>>>(Wq, Wkv, Wo, sgu, x, ln1);

    // ---- attention block (fp16 tensor cores) ----
    // combined q|k|v projection: one GEMM, N=3072
    hgemm_k<4><<<dim3(QKV / 128, TT / 128), 256, H_SMEM>>>(
        (const __half*)p_hn16, (const __half*)p_wqkv16, nullptr, (__half*)p_qkv16,
        QKV, nullptr);
    flash16_k<<<dim3(SS / 64, NHD, BB), 128, FL_SMEM>>>(
        (const __half*)p_qkv16, (__half*)p_attn16);
    hgemm_k<1><<<dim3(HH / 128, TT / 128), 256, H_SMEM>>>(
        (const __half*)p_attn16, (const __half*)p_wo16, (float*)p_x1, nullptr,
        HH, x);

    // ---- MoE block (tf32; W fed raw) ----
    rmsnorm2_k<<<TT, 256>>>((const float*)p_x1, ln2, (float*)p_h2, (float*)p_h2r);
    gate_k<<<TT / 8, 256>>>((const float*)p_h2, gw);
    mma_gemm_k<5><<<dim3((2 * SHD) / 128, TT / 128), 256, TF_SMEM>>>(
        (const float*)p_h2r, (const float*)p_sgui, nullptr, 2 * SHD, nullptr, 0);
    mma_gemm_k<1><<<dim3(HH / 128, TT / 128), 256, TF_SMEM>>>(
        (const float*)p_actr, sdn, out, HH, (const float*)p_x1, 0);
    mma_gemm_k<2><<<dim3(INTER / 128, CAP / 128, EE), 256, TF_SMEM>>>(
        (const float*)p_h2r, w1, nullptr, INTER, nullptr, (size_t)INTER * HH);
    mma_gemm_k<3><<<dim3(HH / 128, CAP / 128, EE), 256, TF_SMEM>>>(
        nullptr, w2, out, HH, nullptr, (size_t)HH * INTER);
}

// round 17
// speedup vs baseline: 1.1330x; 1.1330x over previous
#include <cuda_runtime.h>
#include <cuda_fp16.h>
#include <math.h>
#include <stdint.h>

// ---------------- problem constants ----------------
#define BB 2
#define SS 1024
#define TT 2048
#define HH 1024
#define NHD 8
#define NOPE 128
#define QHD 192
#define VD 128
#define QP 1024           // packed q cols (rope dims dropped)
#define KVC 2048
#define QKV 3072          // combined q|k|v columns
#define EE 8
#define CAP 2048
#define INTER 1024
#define SHD 1024

// ---------------- device scratch ----------------
__device__ __half g_wqkv16[QKV * HH];     // rows [0,1024)=packed Wq, [1024,3072)=Wkv
__device__ __half g_wo16[HH * HH];
__device__ __half g_hnorm16[TT * HH];
__device__ __half g_qkv16[TT * QKV];
__device__ __half g_attn16[TT * HH];
__device__ float g_x1[TT * HH];
__device__ float g_h2r[TT * HH];          // rounded (GEMM A input)
__device__ float g_actr[TT * SHD];
__device__ float g_midr[(size_t)EE * CAP * INTER];
__device__ float g_sgui[2 * SHD * HH];
__device__ int   g_cnt[EE];
__device__ int   g_tok[EE * CAP];
__device__ float g_coef[EE * CAP];

// ---------------- helpers ----------------
__device__ __forceinline__ uint32_t s2u(const void* p) {
    return (uint32_t)__cvta_generic_to_shared(p);
}
__device__ __forceinline__ unsigned f2tf(float f) {
    unsigned r; asm("cvt.rna.tf32.f32 %0, %1;" : "=r"(r) : "f"(f)); return r;
}
__device__ __forceinline__ float f2tf_f(float f) {
    return __uint_as_float(f2tf(f));
}
__device__ __forceinline__ void mma_tf32(float* c, const unsigned* a, const unsigned* b) {
    asm volatile("mma.sync.aligned.m16n8k8.row.col.f32.tf32.tf32.f32 "
                 "{%0,%1,%2,%3},{%4,%5,%6,%7},{%8,%9},{%0,%1,%2,%3};"
                 : "+f"(c[0]), "+f"(c[1]), "+f"(c[2]), "+f"(c[3])
                 : "r"(a[0]), "r"(a[1]), "r"(a[2]), "r"(a[3]), "r"(b[0]), "r"(b[1]));
}
__device__ __forceinline__ void mma16(float* c, const unsigned* a, const unsigned* b) {
    asm volatile("mma.sync.aligned.m16n8k16.row.col.f32.f16.f16.f32 "
                 "{%0,%1,%2,%3},{%4,%5,%6,%7},{%8,%9},{%0,%1,%2,%3};"
                 : "+f"(c[0]), "+f"(c[1]), "+f"(c[2]), "+f"(c[3])
                 : "r"(a[0]), "r"(a[1]), "r"(a[2]), "r"(a[3]), "r"(b[0]), "r"(b[1]));
}
__device__ __forceinline__ void ldsm4(unsigned* r, uint32_t a) {
    asm volatile("ldmatrix.sync.aligned.m8n8.x4.shared.b16 {%0,%1,%2,%3},[%4];"
                 : "=r"(r[0]), "=r"(r[1]), "=r"(r[2]), "=r"(r[3]) : "r"(a));
}
__device__ __forceinline__ void ldsm4t(unsigned* r, uint32_t a) {
    asm volatile("ldmatrix.sync.aligned.m8n8.x4.trans.shared.b16 {%0,%1,%2,%3},[%4];"
                 : "=r"(r[0]), "=r"(r[1]), "=r"(r[2]), "=r"(r[3]) : "r"(a));
}
__device__ __forceinline__ void cpa16(uint32_t d, const void* s) {
    asm volatile("cp.async.cg.shared.global [%0], [%1], 16;" :: "r"(d), "l"(s));
}
__device__ __forceinline__ void cpa_commit() { asm volatile("cp.async.commit_group;"); }
template <int N> __device__ __forceinline__ void cpa_wait() {
    asm volatile("cp.async.wait_group %0;" :: "n"(N));
}
__device__ __forceinline__ unsigned h2u(__half2 h) { return *(unsigned*)&h; }

// ---------------- fused prologue kernel ----------------
__device__ __forceinline__ void cv16h(const float* __restrict__ sp, __half* __restrict__ dp) {
    float4 a0 = *(const float4*)sp;
    float4 a1 = *(const float4*)(sp + 4);
    float4 a2 = *(const float4*)(sp + 8);
    float4 a3 = *(const float4*)(sp + 12);
    __half2 h[8] = {__floats2half2_rn(a0.x, a0.y), __floats2half2_rn(a0.z, a0.w),
                    __floats2half2_rn(a1.x, a1.y), __floats2half2_rn(a1.z, a1.w),
                    __floats2half2_rn(a2.x, a2.y), __floats2half2_rn(a2.z, a2.w),
                    __floats2half2_rn(a3.x, a3.y), __floats2half2_rn(a3.z, a3.w)};
    *(uint4*)dp       = *(uint4*)h;
    *(uint4*)(dp + 8) = *(uint4*)(h + 4);
}
__global__ void fused_pro_k(const float* __restrict__ Wq, const float* __restrict__ Wkv,
                            const float* __restrict__ Wo, const float* __restrict__ sgu,
                            const float* __restrict__ x, const float* __restrict__ ln1) {
    int b = blockIdx.x, t = threadIdx.x;
    if (b == 0 && t < EE) g_cnt[t] = 0;     // router counters (consumed much later)
    if (b < 256) {
        int i = (b * 256 + t) * 16;
        int r = i >> 10, c = i & 1023;
        int sr = (r >> 7) * QHD + (r & 127);
        cv16h(Wq + (size_t)sr * HH + c, g_wqkv16 + i);
    } else if (b < 768) {
        int i = ((b - 256) * 256 + t) * 16;
        cv16h(Wkv + i, g_wqkv16 + (size_t)QP * HH + i);
    } else if (b < 1024) {
        int i = ((b - 768) * 256 + t) * 16;
        cv16h(Wo + i, g_wo16 + i);
    } else if (b < 1536) {
        int i = ((b - 1024) * 256 + t) * 16;
        int row = i >> 10, c = i & 1023;
        int srow = (row & 1) ? (SHD + (row >> 1)) : (row >> 1);
        const float* sp = sgu + (size_t)srow * HH + c;
        float4 a = *(const float4*)sp;
        float4 bq = *(const float4*)(sp + 4);
        float4 cc = *(const float4*)(sp + 8);
        float4 d = *(const float4*)(sp + 12);
        *(float4*)(g_sgui + i)      = make_float4(f2tf_f(a.x), f2tf_f(a.y), f2tf_f(a.z), f2tf_f(a.w));
        *(float4*)(g_sgui + i + 4)  = make_float4(f2tf_f(bq.x), f2tf_f(bq.y), f2tf_f(bq.z), f2tf_f(bq.w));
        *(float4*)(g_sgui + i + 8)  = make_float4(f2tf_f(cc.x), f2tf_f(cc.y), f2tf_f(cc.z), f2tf_f(cc.w));
        *(float4*)(g_sgui + i + 12) = make_float4(f2tf_f(d.x), f2tf_f(d.y), f2tf_f(d.z), f2tf_f(d.w));
    } else {
        int row = b - 1536;
        const float* xr = x + (size_t)row * HH;
        float v[4];
        float s = 0.f;
#pragma unroll
        for (int l = 0; l < 4; l++) {
            v[l] = xr[t + l * 256];
            s += v[l] * v[l];
        }
        __shared__ float red[256];
        red[t] = s;
        __syncthreads();
        for (int off = 128; off > 0; off >>= 1) {
            if (t < off) red[t] += red[t + off];
            __syncthreads();
        }
        float scale = rsqrtf(red[0] * (1.0f / HH) + 1e-6f);
#pragma unroll
        for (int l = 0; l < 4; l++) {
            int i = t + l * 256;
            g_hnorm16[(size_t)row * HH + i] = __float2half_rn(v[l] * scale * ln1[i]);
        }
    }
}

// ---------------- RMSNorm #2 + router + out=x1 init ----------------
__global__ void rmsnorm2_k(const float* __restrict__ x, const float* __restrict__ w,
                           const float* __restrict__ gw,
                           float* __restrict__ y32r, float* __restrict__ out) {
    int row = blockIdx.x;
    int t = threadIdx.x;
    const float* xr = x + (size_t)row * HH;
    float v[4];
    float s = 0.f;
#pragma unroll
    for (int l = 0; l < 4; l++) {
        v[l] = xr[t + l * 256];
        s += v[l] * v[l];
    }
    __shared__ float red[256];
    red[t] = s;
    __syncthreads();
    for (int off = 128; off > 0; off >>= 1) {
        if (t < off) red[t] += red[t + off];
        __syncthreads();
    }
    float scale = rsqrtf(red[0] * (1.0f / HH) + 1e-6f);
    float o[4];
#pragma unroll
    for (int l = 0; l < 4; l++) {
        int i = t + l * 256;
        o[l] = v[l] * scale * w[i];
        y32r[(size_t)row * HH + i] = f2tf_f(o[l]);
        out[(size_t)row * HH + i] = v[l];          // residual init
    }
    // gate logits (8 experts), per-thread partials then reduce
    float pl[EE];
#pragma unroll
    for (int e = 0; e < EE; e++) {
        float acc = 0.f;
#pragma unroll
        for (int l = 0; l < 4; l++)
            acc = fmaf(o[l], gw[e * HH + t + l * 256], acc);
#pragma unroll
        for (int off = 16; off >= 1; off >>= 1)
            acc += __shfl_xor_sync(0xffffffffu, acc, off);
        pl[e] = acc;     // lane-uniform within warp
    }
    __shared__ float wred[8][EE];
    int warp = t >> 5;
    if ((t & 31) == 0)
#pragma unroll
        for (int e = 0; e < EE; e++) wred[warp][e] = pl[e];
    __syncthreads();
    if (t == 0) {
        float logits[EE];
#pragma unroll
        for (int e = 0; e < EE; e++) {
            float a = 0.f;
#pragma unroll
            for (int wi = 0; wi < 8; wi++) a += wred[wi][e];
            logits[e] = a;
        }
        int i0 = 0; float v0 = logits[0];
#pragma unroll
        for (int e = 1; e < EE; e++)
            if (logits[e] > v0) { v0 = logits[e]; i0 = e; }
        int i1 = -1; float v1 = -1e30f;
#pragma unroll
        for (int e = 0; e < EE; e++)
            if (e != i0 && logits[e] > v1) { v1 = logits[e]; i1 = e; }
        float r = __expf(v1 - v0);
        float z = 1.f + r;
        float w0 = 1.f / z, w1 = r / z;
        int p0 = atomicAdd(&g_cnt[i0], 1);
        g_tok[i0 * CAP + p0] = row; g_coef[i0 * CAP + p0] = w0;
        int p1 = atomicAdd(&g_cnt[i1], 1);
        g_tok[i1 * CAP + p1] = row; g_coef[i1 * CAP + p1] = w1;
    }
}

// ================= tf32 GEMM body (device function) =================
// MODE 2 expert-up silu->g_midr / 3 expert-down atomic / 5 gate_up+GLU->g_actr
// MODE 6 shared_down: atomicAdd into C (out pre-initialized to x1)
#define SMS 20
#define GTILE (128 * SMS)

template <int MODE>
__device__ __forceinline__ void gemm_body(
    int e, int m0, int n0,
    const float* __restrict__ A, const float* __restrict__ W,
    float* __restrict__ C, int N, size_t estride,
    float* sA, float* sW, int* s_tok, float* s_cf)
{
    const int tid = threadIdx.x;

    if (MODE == 2 || MODE == 3) {
        int n_e = g_cnt[e];
        if (m0 >= n_e) return;
        if (tid < 128) {
            int i = m0 + tid;
            bool ok = i < n_e;
            s_tok[tid] = ok ? g_tok[e * CAP + i] : -1;
            if (MODE == 3) s_cf[tid] = ok ? g_coef[e * CAP + i] : 0.f;
        }
        __syncthreads();
    }

    const float* Wbase = W + (size_t)e * estride + (size_t)n0 * 1024;
    const float* Arow  = (MODE == 3) ? (g_midr + ((size_t)e * CAP + m0) * 1024)
                                     : (A + (size_t)m0 * 1024);

    auto issue = [&](int stage, int it) {
        int k0 = it * 16;
        uint32_t da = s2u(sA + stage * GTILE);
        uint32_t dw = s2u(sW + stage * GTILE);
#pragma unroll
        for (int j = 0; j < 2; j++) {
            int q = tid + j * 256;
            int r = q >> 2, c4 = q & 3;
            const float* srcA;
            if (MODE == 2) {
                int tk = s_tok[r]; if (tk < 0) tk = 0;
                srcA = A + (size_t)tk * 1024 + k0 + c4 * 4;
            } else {
                srcA = Arow + (size_t)r * 1024 + k0 + c4 * 4;
            }
            uint32_t off = (uint32_t)(r * SMS + c4 * 4) * 4;
            cpa16(da + off, srcA);
            cpa16(dw + off, Wbase + (size_t)r * 1024 + k0 + c4 * 4);
        }
        cpa_commit();
    };

    const int wid = tid >> 5, lane = tid & 31;
    const int wm = wid & 3, wn = wid >> 2;
    const int lr = lane >> 2, lc = lane & 3;

    float acc[2][8][4] = {};

    issue(0, 0);
    issue(1, 1);
    for (int it = 0; it < 64; ++it) {
        int cur = it % 3;
        cpa_wait<1>();
        __syncthreads();
        if (it + 2 < 64) issue((it + 2) % 3, it + 2);
        const float* As = sA + cur * GTILE;
        const float* Ws = sW + cur * GTILE;
#pragma unroll
        for (int ks = 0; ks < 16; ks += 8) {
            unsigned af[2][4];
#pragma unroll
            for (int mt = 0; mt < 2; mt++) {
                int row = wm * 32 + mt * 16 + lr;
                int k = ks + lc;
                af[mt][0] = __float_as_uint(As[row * SMS + k]);
                af[mt][1] = __float_as_uint(As[(row + 8) * SMS + k]);
                af[mt][2] = __float_as_uint(As[row * SMS + k + 4]);
                af[mt][3] = __float_as_uint(As[(row + 8) * SMS + k + 4]);
            }
#pragma unroll
            for (int nt = 0; nt < 8; nt++) {
                int n = wn * 64 + nt * 8 + lr;
                int k = ks + lc;
                unsigned bf[2];
                bf[0] = __float_as_uint(Ws[n * SMS + k]);
                bf[1] = __float_as_uint(Ws[n * SMS + k + 4]);
                mma_tf32(acc[0][nt], af[0], bf);
                mma_tf32(acc[1][nt], af[1], bf);
            }
        }
    }

#pragma unroll
    for (int mt = 0; mt < 2; mt++)
#pragma unroll
    for (int i = 0; i < 2; i++) {
        int rloc = wm * 32 + mt * 16 + lr + i * 8;
#pragma unroll
        for (int nt = 0; nt < 8; nt++) {
            float v0 = acc[mt][nt][2 * i], v1 = acc[mt][nt][2 * i + 1];
            int col = n0 + wn * 64 + nt * 8 + 2 * lc;
            if (MODE == 6) {
                atomicAdd(&C[(size_t)(m0 + rloc) * N + col],     v0);
                atomicAdd(&C[(size_t)(m0 + rloc) * N + col + 1], v1);
            } else if (MODE == 5) {
                float o = v0 / (1.f + __expf(-v0)) * v1;
                g_actr[(size_t)(m0 + rloc) * SHD + (col >> 1)] = f2tf_f(o);
            } else if (MODE == 2) {
                if (s_tok[rloc] >= 0) {
                    float o0 = v0 / (1.f + __expf(-v0));
                    float o1 = v1 / (1.f + __expf(-v1));
                    float* mr = g_midr + ((size_t)e * CAP + m0 + rloc) * 1024;
                    *(float2*)&mr[col] = make_float2(f2tf_f(o0), f2tf_f(o1));
                }
            } else {  // MODE 3
                int tk = s_tok[rloc];
                if (tk >= 0) {
                    float cf = s_cf[rloc];
                    atomicAdd(&C[(size_t)tk * 1024 + col],     cf * v0);
                    atomicAdd(&C[(size_t)tk * 1024 + col + 1], cf * v1);
                }
            }
        }
    }
}

// fused MoE up phase: z==8 -> gate_up+GLU (x<16); z<8 -> expert-up (x<8)
__global__ void __launch_bounds__(256, 2) moe_up_k(
    const float* __restrict__ h2r, const float* __restrict__ sgui,
    const float* __restrict__ w1)
{
    extern __shared__ __align__(16) float dyn[];
    float* sA = dyn;
    float* sW = dyn + 3 * GTILE;
    __shared__ int   s_tok[128];
    __shared__ float s_cf[128];
    if (blockIdx.z == 8) {
        gemm_body<5>(0, blockIdx.y * 128, blockIdx.x * 128,
                     h2r, sgui, nullptr, 2 * SHD, 0, sA, sW, s_tok, s_cf);
    } else {
        if (blockIdx.x >= 8) return;
        gemm_body<2>(blockIdx.z, blockIdx.y * 128, blockIdx.x * 128,
                     h2r, w1, nullptr, INTER, (size_t)INTER * HH, sA, sW, s_tok, s_cf);
    }
}

// fused MoE down phase: z==8 -> shared_down atomic; z<8 -> expert-down atomic
__global__ void __launch_bounds__(256, 2) moe_dn_k(
    const float* __restrict__ actr, const float* __restrict__ sdn,
    const float* __restrict__ w2, float* __restrict__ out)
{
    extern __shared__ __align__(16) float dyn[];
    float* sA = dyn;
    float* sW = dyn + 3 * GTILE;
    __shared__ int   s_tok[128];
    __shared__ float s_cf[128];
    if (blockIdx.z == 8) {
        gemm_body<6>(0, blockIdx.y * 128, blockIdx.x * 128,
                     actr, sdn, out, HH, 0, sA, sW, s_tok, s_cf);
    } else {
        gemm_body<3>(blockIdx.z, blockIdx.y * 128, blockIdx.x * 128,
                     nullptr, w2, out, HH, (size_t)HH * INTER, sA, sW, s_tok, s_cf);
    }
}

// ================= fp16 GEMM (attention path), 3-stage =================
#define HLDA 40
#define HTILE (128 * HLDA)

template <int MODE>
__global__ void __launch_bounds__(256, 2) hgemm_k(
    const __half* __restrict__ A, const __half* __restrict__ W,
    float* __restrict__ C, __half* __restrict__ C16,
    int N, const float* __restrict__ R)
{
    extern __shared__ __align__(16) __half hdyn[];
    __half* sA = hdyn;
    __half* sW = hdyn + 3 * HTILE;

    const int m0 = blockIdx.y * 128;
    const int n0 = blockIdx.x * 128;
    const int tid = threadIdx.x;

    const __half* Wbase = W + (size_t)n0 * 1024;
    const __half* Arow  = A + (size_t)m0 * 1024;

    auto issue = [&](int stage, int it) {
        int k0 = it * 32;
        uint32_t da = s2u(sA + stage * HTILE);
        uint32_t dw = s2u(sW + stage * HTILE);
#pragma unroll
        for (int j = 0; j < 2; j++) {
            int q = tid + j * 256;
            int r = q >> 2, c4 = q & 3;
            uint32_t off = (uint32_t)(r * HLDA + c4 * 8) * 2;
            cpa16(da + off, Arow + (size_t)r * 1024 + k0 + c4 * 8);
            cpa16(dw + off, Wbase + (size_t)r * 1024 + k0 + c4 * 8);
        }
        cpa_commit();
    };

    const int wid = tid >> 5, lane = tid & 31;
    const int wm = wid & 3, wn = wid >> 2;
    const int lr = lane >> 2, lc = lane & 3;
    const int arow = lane & 15, ahalf = lane >> 4;
    const int bg = lane >> 3;
    const int brow = ((bg >> 1) << 3) + (lane & 7);
    const int bcol = (bg & 1) << 3;

    float acc[2][8][4] = {};

    issue(0, 0);
    issue(1, 1);
    for (int it = 0; it < 32; ++it) {
        int cur = it % 3;
        cpa_wait<1>();
        __syncthreads();
        if (it + 2 < 32) issue((it + 2) % 3, it + 2);
        const __half* As = sA + cur * HTILE;
        const __half* Ws = sW + cur * HTILE;
        uint32_t aBase = s2u(As) + (uint32_t)((wm * 32 + arow) * HLDA + ahalf * 8) * 2;
        uint32_t bBase = s2u(Ws) + (uint32_t)((wn * 64 + brow) * HLDA + bcol) * 2;
#pragma unroll
        for (int kc = 0; kc < 2; kc++) {
            unsigned av[2][4];
            ldsm4(av[0], aBase + kc * 32);
            ldsm4(av[1], aBase + kc * 32 + 16 * HLDA * 2);
#pragma unroll
            for (int np = 0; np < 4; np++) {
                unsigned bv[4];
                ldsm4(bv, bBase + kc * 32 + np * 16 * HLDA * 2);
                mma16(acc[0][2 * np],     av[0], bv);
                mma16(acc[0][2 * np + 1], av[0], bv + 2);
                mma16(acc[1][2 * np],     av[1], bv);
                mma16(acc[1][2 * np + 1], av[1], bv + 2);
            }
        }
    }

#pragma unroll
    for (int mt = 0; mt < 2; mt++)
#pragma unroll
    for (int i = 0; i < 2; i++) {
        int rloc = wm * 32 + mt * 16 + lr + i * 8;
#pragma unroll
        for (int nt = 0; nt < 8; nt++) {
            float v0 = acc[mt][nt][2 * i], v1 = acc[mt][nt][2 * i + 1];
            int col = n0 + wn * 64 + nt * 8 + 2 * lc;
            if (MODE == 1) {
                float2 rr = *(const float2*)&R[(size_t)(m0 + rloc) * N + col];
                *(float2*)&C[(size_t)(m0 + rloc) * N + col] = make_float2(v0 + rr.x, v1 + rr.y);
            } else {
                *(__half2*)&C16[(size_t)(m0 + rloc) * N + col] = __floats2half2_rn(v0, v1);
            }
        }
    }
}

// ================= fp16 flash attention =================
#define FLD 136
#define FL_SMEM ((64 + 128 + 128) * FLD * 2)

__global__ void __launch_bounds__(128) flash16_k(const __half* __restrict__ qkv16,
                                                 __half* __restrict__ out16) {
    extern __shared__ __align__(16) __half fsm[];
    __half* Qs = fsm;
    __half* Ks = Qs + 64 * FLD;
    __half* Vs = Ks + 2 * 64 * FLD;

    const int b = blockIdx.z, h = blockIdx.y, qt = blockIdx.x;
    const int tid = threadIdx.x, wid = tid >> 5, lane = tid & 31;
    const int lr = lane >> 2, lc = lane & 3;
    const int t0 = b * SS + qt * 64;
    const float scale = rsqrtf((float)QHD);

    {
        uint32_t qb = s2u(Qs);
#pragma unroll
        for (int j = 0; j < 8; j++) {
            int q = tid + j * 128;
            int r = q >> 4, c = q & 15;
            cpa16(qb + (uint32_t)(r * FLD + c * 8) * 2,
                  qkv16 + (size_t)(t0 + r) * QKV + h * NOPE + c * 8);
        }
    }
    auto issue_kv = [&](int stage, int kt) {
        int k0g = b * SS + kt * 64;
        uint32_t kb = s2u(Ks + stage * 64 * FLD);
        uint32_t vb = s2u(Vs + stage * 64 * FLD);
#pragma unroll
        for (int j = 0; j < 8; j++) {
            int q = tid + j * 128;
            int r = q >> 4, c = q & 15;
            const __half* row = qkv16 + (size_t)(k0g + r) * QKV;
            cpa16(kb + (uint32_t)(r * FLD + c * 8) * 2, row + QP + h * NOPE + c * 8);
            cpa16(vb + (uint32_t)(r * FLD + c * 8) * 2, row + QP + NHD * NOPE + h * VD + c * 8);
        }
        cpa_commit();
    };
    issue_kv(0, 0);

    const int arow = lane & 15, ahalf = lane >> 4;
    const int bg = lane >> 3;
    const int brow = ((bg >> 1) << 3) + (lane & 7);
    const int bcol = (bg & 1) << 3;
    const int vrow = ((bg & 1) << 3) + (lane & 7);
    const int vcol = (bg >> 1) << 3;

    unsigned qf[8][4];
    float m0r = -1e30f, m1r = -1e30f, l0 = 0.f, l1 = 0.f;
    float o[16][4];
#pragma unroll
    for (int nt = 0; nt < 16; nt++)
#pragma unroll
        for (int j = 0; j < 4; j++) o[nt][j] = 0.f;

    for (int kt = 0; kt <= qt; kt++) {
        int cur = kt & 1;
        cpa_wait<0>();
        __syncthreads();
        if (kt < qt) issue_kv(cur ^ 1, kt + 1);
        if (kt == 0) {
            uint32_t qBase = s2u(Qs) + (uint32_t)((wid * 16 + arow) * FLD + ahalf * 8) * 2;
#pragma unroll
            for (int c = 0; c < 8; c++) ldsm4(qf[c], qBase + c * 32);
        }
        const __half* Kb = Ks + cur * 64 * FLD;
        const __half* Vb = Vs + cur * 64 * FLD;

        float sc[8][4] = {};
        uint32_t kBase = s2u(Kb) + (uint32_t)(brow * FLD + bcol) * 2;
#pragma unroll
        for (int c = 0; c < 8; c++) {
#pragma unroll
            for (int np = 0; np < 4; np++) {
                unsigned bv[4];
                ldsm4(bv, kBase + c * 32 + np * 16 * FLD * 2);
                mma16(sc[2 * np],     qf[c], bv);
                mma16(sc[2 * np + 1], qf[c], bv + 2);
            }
        }
#pragma unroll
        for (int nt = 0; nt < 8; nt++)
#pragma unroll
            for (int j = 0; j < 4; j++) sc[nt][j] *= scale;
        if (kt == qt) {
#pragma unroll
            for (int nt = 0; nt < 8; nt++)
#pragma unroll
                for (int j = 0; j < 4; j++) {
                    int colg = nt * 8 + 2 * lc + (j & 1);
                    int rowg = wid * 16 + lr + (j >> 1) * 8;
                    if (colg > rowg) sc[nt][j] = -1e30f;
                }
        }
        float mx0 = -1e30f, mx1 = -1e30f;
#pragma unroll
        for (int nt = 0; nt < 8; nt++) {
            mx0 = fmaxf(mx0, fmaxf(sc[nt][0], sc[nt][1]));
            mx1 = fmaxf(mx1, fmaxf(sc[nt][2], sc[nt][3]));
        }
        mx0 = fmaxf(mx0, __shfl_xor_sync(0xffffffffu, mx0, 1));
        mx0 = fmaxf(mx0, __shfl_xor_sync(0xffffffffu, mx0, 2));
        mx1 = fmaxf(mx1, __shfl_xor_sync(0xffffffffu, mx1, 1));
        mx1 = fmaxf(mx1, __shfl_xor_sync(0xffffffffu, mx1, 2));
        float mn0 = fmaxf(m0r, mx0), mn1 = fmaxf(m1r, mx1);
        float a0 = __expf(m0r - mn0), a1 = __expf(m1r - mn1);
        float s0 = 0.f, s1 = 0.f;
#pragma unroll
        for (int nt = 0; nt < 8; nt++) {
            sc[nt][0] = __expf(sc[nt][0] - mn0);
            sc[nt][1] = __expf(sc[nt][1] - mn0);
            sc[nt][2] = __expf(sc[nt][2] - mn1);
            sc[nt][3] = __expf(sc[nt][3] - mn1);
            s0 += sc[nt][0] + sc[nt][1];
            s1 += sc[nt][2] + sc[nt][3];
        }
        s0 += __shfl_xor_sync(0xffffffffu, s0, 1);
        s0 += __shfl_xor_sync(0xffffffffu, s0, 2);
        s1 += __shfl_xor_sync(0xffffffffu, s1, 1);
        s1 += __shfl_xor_sync(0xffffffffu, s1, 2);
        l0 = l0 * a0 + s0; l1 = l1 * a1 + s1;
        m0r = mn0; m1r = mn1;
#pragma unroll
        for (int nt = 0; nt < 16; nt++) {
            o[nt][0] *= a0; o[nt][1] *= a0;
            o[nt][2] *= a1; o[nt][3] *= a1;
        }
        uint32_t vBase = s2u(Vb) + (uint32_t)(vrow * FLD + vcol) * 2;
#pragma unroll
        for (int c = 0; c < 4; c++) {
            unsigned pa[4];
            pa[0] = h2u(__floats2half2_rn(sc[2 * c][0],     sc[2 * c][1]));
            pa[1] = h2u(__floats2half2_rn(sc[2 * c][2],     sc[2 * c][3]));
            pa[2] = h2u(__floats2half2_rn(sc[2 * c + 1][0], sc[2 * c + 1][1]));
            pa[3] = h2u(__floats2half2_rn(sc[2 * c + 1][2], sc[2 * c + 1][3]));
#pragma unroll
            for (int nv = 0; nv < 8; nv++) {
                unsigned bv[4];
                ldsm4t(bv, vBase + (uint32_t)(c * 16 * FLD + nv * 16) * 2);
                mma16(o[2 * nv],     pa, bv);
                mma16(o[2 * nv + 1], pa, bv + 2);
            }
        }
    }

    float inv0 = 1.f / l0, inv1 = 1.f / l1;
    int r0 = t0 + wid * 16 + lr, r1 = r0 + 8;
#pragma unroll
    for (int nt = 0; nt < 16; nt++) {
        int col = h * VD + nt * 8 + 2 * lc;
        *(__half2*)&out16[(size_t)r0 * HH + col] = __floats2half2_rn(o[nt][0] * inv0, o[nt][1] * inv0);
        *(__half2*)&out16[(size_t)r1 * HH + col] = __floats2half2_rn(o[nt][2] * inv1, o[nt][3] * inv1);
    }
}

// ---------------- launch ----------------
extern "C" void kernel_launch(void* const* d_in, const int* in_sizes, int n_in,
                              void* d_out, int out_size) {
    const float* x   = (const float*)d_in[0];
    const float* ln1 = (const float*)d_in[2];
    const float* ln2 = (const float*)d_in[3];
    const float* Wq  = (const float*)d_in[4];
    const float* Wkv = (const float*)d_in[5];
    const float* Wo  = (const float*)d_in[6];
    const float* gw  = (const float*)d_in[7];
    const float* w1  = (const float*)d_in[8];
    const float* w2  = (const float*)d_in[9];
    const float* sgu = (const float*)d_in[10];
    const float* sdn = (const float*)d_in[11];
    float* out = (float*)d_out;

    void *p_wqkv16, *p_wo16, *p_hn16, *p_qkv16, *p_attn16;
    void *p_x1, *p_h2r, *p_actr, *p_sgui;
    cudaGetSymbolAddress(&p_wqkv16, g_wqkv16);
    cudaGetSymbolAddress(&p_wo16,   g_wo16);
    cudaGetSymbolAddress(&p_hn16,   g_hnorm16);
    cudaGetSymbolAddress(&p_qkv16,  g_qkv16);
    cudaGetSymbolAddress(&p_attn16, g_attn16);
    cudaGetSymbolAddress(&p_x1,   g_x1);
    cudaGetSymbolAddress(&p_h2r,  g_h2r);
    cudaGetSymbolAddress(&p_actr, g_actr);
    cudaGetSymbolAddress(&p_sgui, g_sgui);

    const int TF_SMEM = 6 * GTILE * 4;
    const int H_SMEM  = 6 * HTILE * 2;
    static bool s_init = false;
    if (!s_init) {
        s_init = true;
        cudaFuncSetAttribute(moe_up_k,   cudaFuncAttributeMaxDynamicSharedMemorySize, TF_SMEM);
        cudaFuncSetAttribute(moe_dn_k,   cudaFuncAttributeMaxDynamicSharedMemorySize, TF_SMEM);
        cudaFuncSetAttribute(hgemm_k<1>, cudaFuncAttributeMaxDynamicSharedMemorySize, H_SMEM);
        cudaFuncSetAttribute(hgemm_k<4>, cudaFuncAttributeMaxDynamicSharedMemorySize, H_SMEM);
        cudaFuncSetAttribute(flash16_k,  cudaFuncAttributeMaxDynamicSharedMemorySize, FL_SMEM);
    }

    // fused prologue (also zeroes router counters)
    fused_pro_k<<<3584, 256>>>(Wq, Wkv, Wo, sgu, x, ln1);

    // ---- attention block ----
    hgemm_k<4><<<dim3(QKV / 128, TT / 128), 256, H_SMEM>>>(
        (const __half*)p_hn16, (const __half*)p_wqkv16, nullptr, (__half*)p_qkv16,
        QKV, nullptr);
    flash16_k<<<dim3(SS / 64, NHD, BB), 128, FL_SMEM>>>(
        (const __half*)p_qkv16, (__half*)p_attn16);
    hgemm_k<1><<<dim3(HH / 128, TT / 128), 256, H_SMEM>>>(
        (const __half*)p_attn16, (const __half*)p_wo16, (float*)p_x1, nullptr,
        HH, x);

    // ---- MoE block (tf32; single stream, fused wave-packed kernels) ----
    rmsnorm2_k<<<TT, 256>>>((const float*)p_x1, ln2, gw, (float*)p_h2r, out);
    moe_up_k<<<dim3(16, 16, 9), 256, TF_SMEM>>>(
        (const float*)p_h2r, (const float*)p_sgui, w1);
    moe_dn_k<<<dim3(8, 16, 9), 256, TF_SMEM>>>(
        (const float*)p_actr, sdn, w2, out);
}